// round 3
// baseline (speedup 1.0000x reference)
#include <cuda_runtime.h>
#include <math.h>

// Problem constants (fixed shapes per reference)
#define BN 8192          // batch
#define DK 256           // feature dim
#define NTILES 64        // BN / 128
#define TEMP_INV 14.2857142857142857f   // 1/0.07

// ---------------- static device scratch (no allocations allowed) ----------------
__device__ float g_zn[BN * DK];                 // normalized z_flowed (8 MB)
__device__ unsigned char g_ao[BN];              // allones flag per row
__device__ float g_pall[NTILES * BN];           // partial all-sums  [jtile][row] (2 MB)
__device__ float g_ppos[NTILES * BN];           // partial pos-sums  [jtile][row] (2 MB)
__device__ float g_rowloss[BN];
__device__ unsigned int g_rowvalid[BN];

// ---------------- kernel 1: L2-normalize rows + allones flag ----------------
__global__ void k_norm(const float* __restrict__ zf, const float* __restrict__ attr) {
    int row = blockIdx.x;
    int tid = threadIdx.x;           // 256 threads = DK
    float v = zf[row * DK + tid];
    float ss = v * v;
    #pragma unroll
    for (int o = 16; o; o >>= 1) ss += __shfl_xor_sync(0xffffffffu, ss, o);
    __shared__ float ws[8];
    __shared__ float s_inv;
    if ((tid & 31) == 0) ws[tid >> 5] = ss;
    __syncthreads();
    if (tid == 0) {
        float t = 0.f;
        #pragma unroll
        for (int i = 0; i < 8; i++) t += ws[i];
        float n = fmaxf(sqrtf(t), 1e-12f);
        s_inv = 1.0f / n;
        const float* a = attr + row * 4;
        g_ao[row] = ((a[0] + a[1] + a[2] + a[3]) == 4.0f) ? 1 : 0;
    }
    __syncthreads();
    g_zn[row * DK + tid] = v * s_inv;
}

// ---------------- kernel 2: fused gram tile + exp + masked row-sums ----------------
// Block = one 128x128 tile of sim. 256 threads, 8x8 accumulators per thread.
// Smem tiles stored k-major [k][row] (padded 132) for conflict-free LDS.128.
#define KC 32
__global__ __launch_bounds__(256) void k_gram() {
    __shared__ float As[KC][132];
    __shared__ float Bs[KC][132];
    __shared__ unsigned char s_aoi[128];
    __shared__ unsigned char s_aoj[128];

    const int it = blockIdx.x, jt = blockIdx.y;
    const int tid = threadIdx.x;
    const int trow = tid >> 4;          // 0..15
    const int tcol = tid & 15;          // 0..15
    const int i0 = it * 128, j0 = jt * 128;

    if (tid < 128) s_aoi[tid] = g_ao[i0 + tid];
    else           s_aoj[tid - 128] = g_ao[j0 + (tid - 128)];

    float acc[8][8];
    #pragma unroll
    for (int m = 0; m < 8; m++)
        #pragma unroll
        for (int n = 0; n < 8; n++) acc[m][n] = 0.f;

    // loader mapping: each thread loads 4 float4 from A-rows and 4 from B-rows per chunk
    const int lr = tid >> 3;            // base row 0..31
    const int lc = (tid & 7) * 4;       // k offset within chunk

    for (int kc = 0; kc < DK; kc += KC) {
        __syncthreads();   // protect smem from previous iteration's readers
        #pragma unroll
        for (int u = 0; u < 4; u++) {
            int r = lr + 32 * u;
            float4 av = *reinterpret_cast<const float4*>(&g_zn[(i0 + r) * DK + kc + lc]);
            float4 bv = *reinterpret_cast<const float4*>(&g_zn[(j0 + r) * DK + kc + lc]);
            As[lc + 0][r] = av.x; As[lc + 1][r] = av.y; As[lc + 2][r] = av.z; As[lc + 3][r] = av.w;
            Bs[lc + 0][r] = bv.x; Bs[lc + 1][r] = bv.y; Bs[lc + 2][r] = bv.z; Bs[lc + 3][r] = bv.w;
        }
        __syncthreads();
        #pragma unroll
        for (int k = 0; k < KC; k++) {
            float4 a0 = *reinterpret_cast<const float4*>(&As[k][trow * 4]);
            float4 a1 = *reinterpret_cast<const float4*>(&As[k][64 + trow * 4]);
            float4 b0 = *reinterpret_cast<const float4*>(&Bs[k][tcol * 4]);
            float4 b1 = *reinterpret_cast<const float4*>(&Bs[k][64 + tcol * 4]);
            float a[8] = {a0.x, a0.y, a0.z, a0.w, a1.x, a1.y, a1.z, a1.w};
            float b[8] = {b0.x, b0.y, b0.z, b0.w, b1.x, b1.y, b1.z, b1.w};
            #pragma unroll
            for (int m = 0; m < 8; m++)
                #pragma unroll
                for (int n = 0; n < 8; n++) acc[m][n] += a[m] * b[n];
        }
    }

    // epilogue: exp + masks + per-row sums, reduce across the 16 tcol lanes
    #pragma unroll
    for (int m = 0; m < 8; m++) {
        int rloc = (m < 4) ? (trow * 4 + m) : (64 + trow * 4 + (m - 4));
        int gi = i0 + rloc;
        bool aoi = (s_aoi[rloc] != 0);
        float sa = 0.f, sp = 0.f;
        #pragma unroll
        for (int n = 0; n < 8; n++) {
            int cloc = (n < 4) ? (tcol * 4 + n) : (64 + tcol * 4 + (n - 4));
            int gj = j0 + cloc;
            float e = __expf(acc[m][n] * TEMP_INV);
            if (gi == gj) e = 0.f;          // zero diagonal (excluded from both sums)
            sa += e;
            if (aoi && s_aoj[cloc]) sp += e;
        }
        // reduce over the 16 lanes sharing this row (stays within 16-lane group)
        #pragma unroll
        for (int o = 8; o; o >>= 1) {
            sa += __shfl_xor_sync(0xffffffffu, sa, o);
            sp += __shfl_xor_sync(0xffffffffu, sp, o);
        }
        if (tcol == 0) {
            g_pall[jt * BN + gi] = sa;
            g_ppos[jt * BN + gi] = sp;
        }
    }
}

// ---------------- kernel 3: per-row loss (deterministic fixed-order sum) ----------------
__global__ void k_rowloss() {
    int i = blockIdx.x * blockDim.x + threadIdx.x;  // 0..8191
    float all = 0.f, pos = 0.f;
    #pragma unroll 4
    for (int t = 0; t < NTILES; t++) {
        all += g_pall[t * BN + i];
        pos += g_ppos[t * BN + i];
    }
    bool valid = (g_ao[i] != 0) && (pos > 0.f);
    g_rowloss[i]  = valid ? (logf(all) - logf(pos)) : 0.f;   // -(log pos - log all)
    g_rowvalid[i] = valid ? 1u : 0u;
}

// ---------------- kernel 4: final reduction to scalar ----------------
__global__ void k_final(float* __restrict__ out) {
    __shared__ float ssum[256];
    __shared__ unsigned int scnt[256];
    int tid = threadIdx.x;
    float s = 0.f; unsigned int c = 0u;
    for (int i = tid; i < BN; i += 256) { s += g_rowloss[i]; c += g_rowvalid[i]; }
    ssum[tid] = s; scnt[tid] = c;
    __syncthreads();
    for (int o = 128; o; o >>= 1) {
        if (tid < o) { ssum[tid] += ssum[tid + o]; scnt[tid] += scnt[tid + o]; }
        __syncthreads();
    }
    if (tid == 0) out[0] = (scnt[0] > 0u) ? (ssum[0] / (float)scnt[0]) : 0.f;
}

// ---------------- entry point ----------------
extern "C" void kernel_launch(void* const* d_in, const int* in_sizes, int n_in,
                              void* d_out, int out_size) {
    // metadata order: z_original (unused), z_flowed, attributes
    const float* zf   = (const float*)d_in[1];
    const float* attr = (const float*)d_in[2];
    float* out = (float*)d_out;

    k_norm<<<BN, DK>>>(zf, attr);
    k_gram<<<dim3(NTILES, NTILES), 256>>>();
    k_rowloss<<<BN / 256, 256>>>();
    k_final<<<1, 256>>>(out);
}

// round 6
// speedup vs baseline: 1.8527x; 1.8527x over previous
#include <cuda_runtime.h>
#include <math.h>

#define BN 8192
#define DK 256
#define NTILES 64
#define TEMP_INV 14.2857142857142857f   // 1/0.07

// ---------------- static device scratch ----------------
__device__ float g_zn[BN * DK];                 // normalized z_flowed (8 MB)
__device__ unsigned char g_ao[BN];              // allones flag per row
__device__ float g_pall[NTILES * BN];           // partial all-sums  [colTile][row]
__device__ float g_ppos[NTILES * BN];           // partial pos-sums  [colTile][row]
__device__ float g_rowloss[BN];
__device__ unsigned int g_rowvalid[BN];

// ---------------- kernel 1: L2-normalize rows + allones flag ----------------
__global__ void k_norm(const float* __restrict__ zf, const float* __restrict__ attr) {
    int row = blockIdx.x;
    int tid = threadIdx.x;           // 256 threads = DK
    float v = zf[row * DK + tid];
    float ss = v * v;
    #pragma unroll
    for (int o = 16; o; o >>= 1) ss += __shfl_xor_sync(0xffffffffu, ss, o);
    __shared__ float ws[8];
    __shared__ float s_inv;
    if ((tid & 31) == 0) ws[tid >> 5] = ss;
    __syncthreads();
    if (tid == 0) {
        float t = 0.f;
        #pragma unroll
        for (int i = 0; i < 8; i++) t += ws[i];
        float n = fmaxf(sqrtf(t), 1e-12f);
        s_inv = 1.0f / n;
        const float* a = attr + row * 4;
        g_ao[row] = ((a[0] + a[1] + a[2] + a[3]) == 4.0f) ? 1 : 0;
    }
    __syncthreads();
    g_zn[row * DK + tid] = v * s_inv;
}

// ---------------- kernel 2: symmetric gram tile + exp + dual masked sums ----------------
// Only tiles jt >= it are computed. Each block emits:
//   row sums  -> slot [jt][i-rows]   (sum over this tile's j-columns)
//   col sums  -> slot [it][j-rows]   (sum over this tile's i-rows; e is symmetric)
// Diagonal tiles emit row sums only. Every slot written exactly once -> deterministic.
#define KC 32
__global__ __launch_bounds__(256) void k_gram() {
    __shared__ float As[KC][132];
    __shared__ float Bs[KC][132];
    __shared__ unsigned char s_aoi[128];
    __shared__ unsigned char s_aoj[128];

    const int it = blockIdx.x, jt = blockIdx.y;
    if (jt < it) return;                 // block-uniform early exit

    const int tid = threadIdx.x;
    const int trow = tid >> 4;           // 0..15
    const int tcol = tid & 15;           // 0..15
    const int i0 = it * 128, j0 = jt * 128;

    if (tid < 128) s_aoi[tid] = g_ao[i0 + tid];
    else           s_aoj[tid - 128] = g_ao[j0 + (tid - 128)];

    float acc[8][8];
    #pragma unroll
    for (int m = 0; m < 8; m++)
        #pragma unroll
        for (int n = 0; n < 8; n++) acc[m][n] = 0.f;

    const int lr = tid >> 3;             // loader base row 0..31
    const int lc = (tid & 7) * 4;        // loader k offset

    for (int kc = 0; kc < DK; kc += KC) {
        __syncthreads();
        #pragma unroll
        for (int u = 0; u < 4; u++) {
            int r = lr + 32 * u;
            float4 av = *reinterpret_cast<const float4*>(&g_zn[(i0 + r) * DK + kc + lc]);
            float4 bv = *reinterpret_cast<const float4*>(&g_zn[(j0 + r) * DK + kc + lc]);
            As[lc + 0][r] = av.x; As[lc + 1][r] = av.y; As[lc + 2][r] = av.z; As[lc + 3][r] = av.w;
            Bs[lc + 0][r] = bv.x; Bs[lc + 1][r] = bv.y; Bs[lc + 2][r] = bv.z; Bs[lc + 3][r] = bv.w;
        }
        __syncthreads();
        #pragma unroll
        for (int k = 0; k < KC; k++) {
            float4 a0 = *reinterpret_cast<const float4*>(&As[k][trow * 4]);
            float4 a1 = *reinterpret_cast<const float4*>(&As[k][64 + trow * 4]);
            float4 b0 = *reinterpret_cast<const float4*>(&Bs[k][tcol * 4]);
            float4 b1 = *reinterpret_cast<const float4*>(&Bs[k][64 + tcol * 4]);
            float a[8] = {a0.x, a0.y, a0.z, a0.w, a1.x, a1.y, a1.z, a1.w};
            float b[8] = {b0.x, b0.y, b0.z, b0.w, b1.x, b1.y, b1.z, b1.w};
            #pragma unroll
            for (int m = 0; m < 8; m++)
                #pragma unroll
                for (int n = 0; n < 8; n++) acc[m][n] += a[m] * b[n];
        }
    }
    __syncthreads();   // tiles no longer needed; smem reused below for col sums

    // ---- epilogue: exp once per element, accumulate row & col partials ----
    float cola[8], colp[8];
    #pragma unroll
    for (int n = 0; n < 8; n++) { cola[n] = 0.f; colp[n] = 0.f; }

    #pragma unroll
    for (int m = 0; m < 8; m++) {
        int rloc = (m < 4) ? (trow * 4 + m) : (64 + trow * 4 + (m - 4));
        int gi = i0 + rloc;
        bool aoi = (s_aoi[rloc] != 0);
        float sa = 0.f, sp = 0.f;
        #pragma unroll
        for (int n = 0; n < 8; n++) {
            int cloc = (n < 4) ? (tcol * 4 + n) : (64 + tcol * 4 + (n - 4));
            int gj = j0 + cloc;
            float e = __expf(acc[m][n] * TEMP_INV);
            if (gi == gj) e = 0.f;                 // zero diagonal
            sa += e;
            if (aoi && s_aoj[cloc]) sp += e;
            cola[n] += e;
            if (aoi) colp[n] += e;
        }
        // row reduction over the 16 tcol lanes (contiguous within warp)
        #pragma unroll
        for (int o = 8; o; o >>= 1) {
            sa += __shfl_xor_sync(0xffffffffu, sa, o);
            sp += __shfl_xor_sync(0xffffffffu, sp, o);
        }
        if (tcol == 0) {
            g_pall[jt * BN + gi] = sa;
            g_ppos[jt * BN + gi] = sp;
        }
    }

    // ---- column sums (rows of the j-tile) via smem; skip on diagonal tiles ----
    if (it != jt) {
        float* sca = &As[0][0];   // 16 x 128 floats (reuse tile smem)
        float* scp = &Bs[0][0];
        #pragma unroll
        for (int n = 0; n < 8; n++) {
            int cloc = (n < 4) ? (tcol * 4 + n) : (64 + tcol * 4 + (n - 4));
            sca[trow * 128 + cloc] = cola[n];
            scp[trow * 128 + cloc] = colp[n];
        }
        __syncthreads();
        if (tid < 128) {
            float ca = 0.f, cp = 0.f;
            #pragma unroll
            for (int r = 0; r < 16; r++) {
                ca += sca[r * 128 + tid];
                cp += scp[r * 128 + tid];
            }
            int gj = j0 + tid;
            g_pall[it * BN + gj] = ca;
            g_ppos[it * BN + gj] = (s_aoj[tid] != 0) ? cp : 0.f;
        }
    }
}

// ---------------- kernel 3: per-row loss (deterministic fixed-order sum) ----------------
__global__ void k_rowloss() {
    int i = blockIdx.x * blockDim.x + threadIdx.x;
    float all = 0.f, pos = 0.f;
    #pragma unroll 4
    for (int t = 0; t < NTILES; t++) {
        all += g_pall[t * BN + i];
        pos += g_ppos[t * BN + i];
    }
    bool valid = (g_ao[i] != 0) && (pos > 0.f);
    g_rowloss[i]  = valid ? (logf(all) - logf(pos)) : 0.f;
    g_rowvalid[i] = valid ? 1u : 0u;
}

// ---------------- kernel 4: final reduction ----------------
__global__ void k_final(float* __restrict__ out) {
    __shared__ float ssum[256];
    __shared__ unsigned int scnt[256];
    int tid = threadIdx.x;
    float s = 0.f; unsigned int c = 0u;
    for (int i = tid; i < BN; i += 256) { s += g_rowloss[i]; c += g_rowvalid[i]; }
    ssum[tid] = s; scnt[tid] = c;
    __syncthreads();
    for (int o = 128; o; o >>= 1) {
        if (tid < o) { ssum[tid] += ssum[tid + o]; scnt[tid] += scnt[tid + o]; }
        __syncthreads();
    }
    if (tid == 0) out[0] = (scnt[0] > 0u) ? (ssum[0] / (float)scnt[0]) : 0.f;
}

// ---------------- entry point ----------------
extern "C" void kernel_launch(void* const* d_in, const int* in_sizes, int n_in,
                              void* d_out, int out_size) {
    const float* zf   = (const float*)d_in[1];
    const float* attr = (const float*)d_in[2];
    float* out = (float*)d_out;

    k_norm<<<BN, DK>>>(zf, attr);
    k_gram<<<dim3(NTILES, NTILES), 256>>>();
    k_rowloss<<<BN / 256, 256>>>();
    k_final<<<1, 256>>>(out);
}

// round 9
// speedup vs baseline: 6.7693x; 3.6537x over previous
#include <cuda_runtime.h>
#include <cuda_fp16.h>
#include <math.h>
#include <stdint.h>

#define BN 8192
#define DK 256
#define NTILES 64
#define TEMP_INV 14.2857142857142857f   // 1/0.07

// ---------------- static device scratch ----------------
__device__ __align__(16) __half g_znh[BN * DK];   // fp16 normalized z_flowed (4 MB)
__device__ unsigned char g_ao[BN];                // allones flag per row
__device__ float g_pall[NTILES * BN];             // partial all-sums  [colTile][row]
__device__ float g_ppos[NTILES * BN];             // partial pos-sums  [colTile][row]
__device__ float g_blocksum[32];
__device__ unsigned int g_blockcnt[32];

__device__ __forceinline__ uint32_t smem_u32(const void* p) {
    uint32_t a;
    asm("{ .reg .u64 t; cvta.to.shared.u64 t, %1; cvt.u32.u64 %0, t; }" : "=r"(a) : "l"(p));
    return a;
}
__device__ __forceinline__ void ldsm_x4(uint32_t& r0, uint32_t& r1, uint32_t& r2, uint32_t& r3,
                                        uint32_t addr) {
    asm volatile("ldmatrix.sync.aligned.m8n8.x4.shared.b16 {%0,%1,%2,%3}, [%4];"
                 : "=r"(r0), "=r"(r1), "=r"(r2), "=r"(r3) : "r"(addr));
}
__device__ __forceinline__ void mma16816(float* d, const uint32_t* a, uint32_t b0, uint32_t b1) {
    asm volatile(
        "mma.sync.aligned.m16n8k16.row.col.f32.f16.f16.f32 "
        "{%0,%1,%2,%3}, {%4,%5,%6,%7}, {%8,%9}, {%0,%1,%2,%3};"
        : "+f"(d[0]), "+f"(d[1]), "+f"(d[2]), "+f"(d[3])
        : "r"(a[0]), "r"(a[1]), "r"(a[2]), "r"(a[3]), "r"(b0), "r"(b1));
}

// smem layout (dynamic)
#define OFF_AOI   0                    // 128 B
#define OFF_AOJ   128                  // 128 B
#define OFF_RPA   512                  // rowpartA [4][128] f32 = 2048
#define OFF_RPP   2560                 // rowpartP [4][128] f32 = 2048
#define OFF_CPA   4608                 // colpartA [2][128] f32 = 1024
#define OFF_CPP   5632                 // colpartP [2][128] f32 = 1024
#define OFF_A     8192                 // A tile: 128 rows x 512 B (swizzled)
#define OFF_B     73728                // B tile: 128 rows x 512 B
#define SMEM_TOTAL 139264

// ---------------- kernel 1: L2-normalize rows (fp16 out) + allones flag ----------------
__global__ void k_norm(const float* __restrict__ zf, const float* __restrict__ attr) {
    int row = blockIdx.x;
    int tid = threadIdx.x;           // 256 = DK
    float v = zf[row * DK + tid];
    float ss = v * v;
    #pragma unroll
    for (int o = 16; o; o >>= 1) ss += __shfl_xor_sync(0xffffffffu, ss, o);
    __shared__ float ws[8];
    __shared__ float s_inv;
    if ((tid & 31) == 0) ws[tid >> 5] = ss;
    __syncthreads();
    if (tid == 0) {
        float t = 0.f;
        #pragma unroll
        for (int i = 0; i < 8; i++) t += ws[i];
        s_inv = 1.0f / fmaxf(sqrtf(t), 1e-12f);
        const float* a = attr + row * 4;
        g_ao[row] = ((a[0] + a[1] + a[2] + a[3]) == 4.0f) ? 1 : 0;
    }
    __syncthreads();
    g_znh[row * DK + tid] = __float2half(v * s_inv);
}

// ---------------- kernel 2: HMMA gram tile + exp + dual masked sums ----------------
// 256 threads = 8 warps, warp grid 2 (rows) x 4 (cols); warp tile 64x32.
__global__ __launch_bounds__(256) void k_gram_mma() {
    extern __shared__ char smem[];
    const int it = blockIdx.x, jt = blockIdx.y;
    if (jt < it) return;

    const uint32_t sbase = smem_u32(smem);
    const int tid = threadIdx.x;
    const int wid = tid >> 5;
    const int lane = tid & 31;
    const int wr = wid & 1;              // warp row (0..1) -> rows wr*64..+63
    const int wc = wid >> 1;             // warp col (0..3) -> cols wc*32..+31
    const int i0 = it * 128, j0 = jt * 128;

    if (tid < 128) smem[OFF_AOI + tid] = (char)g_ao[i0 + tid];
    else           smem[OFF_AOJ + tid - 128] = (char)g_ao[j0 + (tid - 128)];

    // load A/B fp16 tiles (128 rows x 256 halves), 16B-chunk XOR swizzle
    #pragma unroll
    for (int u = 0; u < 16; u++) {
        int idx = tid + 256 * u;          // 0..4095
        int r = idx >> 5;                 // row
        int c = idx & 31;                 // 16B chunk along K
        int phys = (c & ~7) | ((c ^ r) & 7);
        uint4 av = *reinterpret_cast<const uint4*>(&g_znh[(i0 + r) * DK + c * 8]);
        uint4 bv = *reinterpret_cast<const uint4*>(&g_znh[(j0 + r) * DK + c * 8]);
        *reinterpret_cast<uint4*>(smem + OFF_A + r * 512 + phys * 16) = av;
        *reinterpret_cast<uint4*>(smem + OFF_B + r * 512 + phys * 16) = bv;
    }
    __syncthreads();

    float acc[4][4][4];
    #pragma unroll
    for (int mi = 0; mi < 4; mi++)
        #pragma unroll
        for (int ni = 0; ni < 4; ni++)
            #pragma unroll
            for (int e = 0; e < 4; e++) acc[mi][ni][e] = 0.f;

    #pragma unroll
    for (int kk = 0; kk < 16; kk++) {     // 16 halves of K per step
        uint32_t afr[4][4], bfr[2][4];
        const int cch = kk * 2 + (lane >> 4);   // 16B chunk index for this lane
        #pragma unroll
        for (int mi = 0; mi < 4; mi++) {
            int r = wr * 64 + mi * 16 + (lane & 15);
            int phys = (cch & ~7) | ((cch ^ r) & 7);
            ldsm_x4(afr[mi][0], afr[mi][1], afr[mi][2], afr[mi][3],
                    sbase + OFF_A + r * 512 + phys * 16);
        }
        #pragma unroll
        for (int n2 = 0; n2 < 2; n2++) {
            int r = wc * 32 + n2 * 16 + (lane & 15);
            int phys = (cch & ~7) | ((cch ^ r) & 7);
            ldsm_x4(bfr[n2][0], bfr[n2][1], bfr[n2][2], bfr[n2][3],
                    sbase + OFF_B + r * 512 + phys * 16);
        }
        #pragma unroll
        for (int mi = 0; mi < 4; mi++)
            #pragma unroll
            for (int ni = 0; ni < 4; ni++) {
                int n2 = ni >> 1, odd = ni & 1;
                mma16816(acc[mi][ni], afr[mi], bfr[n2][odd], bfr[n2][odd + 2]);
            }
    }

    // ---- epilogue: exp + per-thread row/col partial sums ----
    const int g = lane >> 2;              // 0..7
    const int cp2 = (lane & 3) * 2;       // col pair base
    float rs[8], rp[8], cs[8], cpn[8];
    #pragma unroll
    for (int x = 0; x < 8; x++) { rs[x] = rp[x] = cs[x] = cpn[x] = 0.f; }

    const bool diag = (it == jt);
    #pragma unroll
    for (int mi = 0; mi < 4; mi++) {
        #pragma unroll
        for (int h = 0; h < 2; h++) {
            int rloc = wr * 64 + mi * 16 + h * 8 + g;
            bool aoi_r = smem[OFF_AOI + rloc] != 0;
            #pragma unroll
            for (int ni = 0; ni < 4; ni++) {
                #pragma unroll
                for (int q = 0; q < 2; q++) {
                    int cloc = wc * 32 + ni * 8 + cp2 + q;
                    float v = acc[mi][ni][h * 2 + q];
                    float e = __expf(v * TEMP_INV);
                    if (diag && rloc == cloc) e = 0.f;
                    rs[mi * 2 + h] += e;
                    if (smem[OFF_AOJ + cloc]) rp[mi * 2 + h] += e;
                    cs[ni * 2 + q] += e;
                    if (aoi_r) cpn[ni * 2 + q] += e;
                }
            }
        }
    }

    // row reduce across lane&3 group
    #pragma unroll
    for (int x = 0; x < 8; x++) {
        rs[x] += __shfl_xor_sync(0xffffffffu, rs[x], 1);
        rs[x] += __shfl_xor_sync(0xffffffffu, rs[x], 2);
        rp[x] += __shfl_xor_sync(0xffffffffu, rp[x], 1);
        rp[x] += __shfl_xor_sync(0xffffffffu, rp[x], 2);
    }
    float* rpa = reinterpret_cast<float*>(smem + OFF_RPA);
    float* rpp = reinterpret_cast<float*>(smem + OFF_RPP);
    if ((lane & 3) == 0) {
        #pragma unroll
        for (int mi = 0; mi < 4; mi++)
            #pragma unroll
            for (int h = 0; h < 2; h++) {
                int rloc = wr * 64 + mi * 16 + h * 8 + g;
                rpa[wc * 128 + rloc] = rs[mi * 2 + h];
                rpp[wc * 128 + rloc] = rp[mi * 2 + h];
            }
    }

    // col reduce across lane>>2 group
    #pragma unroll
    for (int x = 0; x < 8; x++) {
        cs[x] += __shfl_xor_sync(0xffffffffu, cs[x], 4);
        cs[x] += __shfl_xor_sync(0xffffffffu, cs[x], 8);
        cs[x] += __shfl_xor_sync(0xffffffffu, cs[x], 16);
        cpn[x] += __shfl_xor_sync(0xffffffffu, cpn[x], 4);
        cpn[x] += __shfl_xor_sync(0xffffffffu, cpn[x], 8);
        cpn[x] += __shfl_xor_sync(0xffffffffu, cpn[x], 16);
    }
    float* cpa = reinterpret_cast<float*>(smem + OFF_CPA);
    float* cpp = reinterpret_cast<float*>(smem + OFF_CPP);
    if (lane < 4) {
        #pragma unroll
        for (int ni = 0; ni < 4; ni++)
            #pragma unroll
            for (int q = 0; q < 2; q++) {
                int cloc = wc * 32 + ni * 8 + lane * 2 + q;
                cpa[wr * 128 + cloc] = cs[ni * 2 + q];
                cpp[wr * 128 + cloc] = cpn[ni * 2 + q];
            }
    }
    __syncthreads();

    if (tid < 128) {
        // row sums for i-tile rows -> slot [jt][i]
        float a = rpa[tid] + rpa[128 + tid] + rpa[256 + tid] + rpa[384 + tid];
        float p = rpp[tid] + rpp[128 + tid] + rpp[256 + tid] + rpp[384 + tid];
        g_pall[jt * BN + i0 + tid] = a;
        g_ppos[jt * BN + i0 + tid] = (smem[OFF_AOI + tid] != 0) ? p : 0.f;
    } else if (it != jt) {
        // column sums (rows of j-tile by symmetry) -> slot [it][j]
        int j = tid - 128;
        float a = cpa[j] + cpa[128 + j];
        float p = cpp[j] + cpp[128 + j];
        g_pall[it * BN + j0 + j] = a;
        g_ppos[it * BN + j0 + j] = (smem[OFF_AOJ + j] != 0) ? p : 0.f;
    }
}

// ---------------- kernel 3: per-row loss + block partial reduction ----------------
__global__ void k_rowloss() {
    int i = blockIdx.x * blockDim.x + threadIdx.x;
    float all = 0.f, pos = 0.f;
    #pragma unroll 4
    for (int t = 0; t < NTILES; t++) {
        all += g_pall[t * BN + i];
        pos += g_ppos[t * BN + i];
    }
    bool valid = (g_ao[i] != 0) && (pos > 0.f);
    float loss = valid ? (logf(all) - logf(pos)) : 0.f;
    unsigned int cnt = valid ? 1u : 0u;
    #pragma unroll
    for (int o = 16; o; o >>= 1) {
        loss += __shfl_xor_sync(0xffffffffu, loss, o);
        cnt  += __shfl_xor_sync(0xffffffffu, cnt, o);
    }
    __shared__ float ws[8];
    __shared__ unsigned int wcv[8];
    int tid = threadIdx.x;
    if ((tid & 31) == 0) { ws[tid >> 5] = loss; wcv[tid >> 5] = cnt; }
    __syncthreads();
    if (tid == 0) {
        float s = 0.f; unsigned int c = 0u;
        #pragma unroll
        for (int k = 0; k < 8; k++) { s += ws[k]; c += wcv[k]; }
        g_blocksum[blockIdx.x] = s;
        g_blockcnt[blockIdx.x] = c;
    }
}

// ---------------- kernel 4: final reduction (1 warp) ----------------
__global__ void k_final(float* __restrict__ out) {
    int tid = threadIdx.x;   // 32
    float s = g_blocksum[tid];
    unsigned int c = g_blockcnt[tid];
    #pragma unroll
    for (int o = 16; o; o >>= 1) {
        s += __shfl_xor_sync(0xffffffffu, s, o);
        c += __shfl_xor_sync(0xffffffffu, c, o);
    }
    if (tid == 0) out[0] = (c > 0u) ? (s / (float)c) : 0.f;
}

// ---------------- entry point ----------------
extern "C" void kernel_launch(void* const* d_in, const int* in_sizes, int n_in,
                              void* d_out, int out_size) {
    const float* zf   = (const float*)d_in[1];
    const float* attr = (const float*)d_in[2];
    float* out = (float*)d_out;

    cudaFuncSetAttribute(k_gram_mma, cudaFuncAttributeMaxDynamicSharedMemorySize, SMEM_TOTAL);

    k_norm<<<BN, DK>>>(zf, attr);
    k_gram_mma<<<dim3(NTILES, NTILES), 256, SMEM_TOTAL>>>();
    k_rowloss<<<BN / 256, 256>>>();
    k_final<<<1, 32>>>(out);
}

// round 10
// speedup vs baseline: 9.2164x; 1.3615x over previous
#include <cuda_runtime.h>
#include <cuda_fp16.h>
#include <math.h>
#include <stdint.h>

#define BN 8192
#define DK 256
#define NTILES 64
#define TEMP_INV 14.2857142857142857f   // 1/0.07

// ---------------- static device scratch ----------------
__device__ __align__(16) __half g_znh[BN * DK];   // fp16 normalized z_flowed (4 MB)
__device__ unsigned char g_ao[BN];                // allones flag per row
__device__ float g_pall[NTILES * BN];             // partial all-sums  [colTile][row]
__device__ float g_ppos[NTILES * BN];             // partial pos-sums  [colTile][row]
__device__ float g_blocksum[32];
__device__ unsigned int g_blockcnt[32];
__device__ unsigned int g_ticket;                 // zero-init; self-resetting

__device__ __forceinline__ uint32_t smem_u32(const void* p) {
    uint32_t a;
    asm("{ .reg .u64 t; cvta.to.shared.u64 t, %1; cvt.u32.u64 %0, t; }" : "=r"(a) : "l"(p));
    return a;
}
__device__ __forceinline__ void ldsm_x4(uint32_t& r0, uint32_t& r1, uint32_t& r2, uint32_t& r3,
                                        uint32_t addr) {
    asm volatile("ldmatrix.sync.aligned.m8n8.x4.shared.b16 {%0,%1,%2,%3}, [%4];"
                 : "=r"(r0), "=r"(r1), "=r"(r2), "=r"(r3) : "r"(addr));
}
__device__ __forceinline__ void mma16816(float* d, const uint32_t* a, uint32_t b0, uint32_t b1) {
    asm volatile(
        "mma.sync.aligned.m16n8k16.row.col.f32.f16.f16.f32 "
        "{%0,%1,%2,%3}, {%4,%5,%6,%7}, {%8,%9}, {%0,%1,%2,%3};"
        : "+f"(d[0]), "+f"(d[1]), "+f"(d[2]), "+f"(d[3])
        : "r"(a[0]), "r"(a[1]), "r"(a[2]), "r"(a[3]), "r"(b0), "r"(b1));
}
__device__ __forceinline__ void cp16(uint32_t dst, const void* src) {
    asm volatile("cp.async.cg.shared.global [%0], [%1], 16;" :: "r"(dst), "l"(src) : "memory");
}
#define CP_COMMIT() asm volatile("cp.async.commit_group;" ::: "memory")
#define CP_WAIT(n)  asm volatile("cp.async.wait_group %0;" :: "n"(n) : "memory")

// smem layout (dynamic): control region then 2x double-buffered A/B chunks
#define OFF_AOI   0                    // 128 B
#define OFF_AOJ   128                  // 128 B
#define OFF_RPA   256                  // rowpartA [4][128] f32 = 2048
#define OFF_RPP   2304                 // rowpartP [4][128] f32 = 2048
#define OFF_CPA   4352                 // colpartA [2][128] f32 = 1024
#define OFF_CPP   5376                 // colpartP [2][128] f32 = 1024
#define OFF_A0    8192                 // chunk buffers: 128 rows x 128 B = 16 KB each
#define OFF_B0    24576
#define OFF_A1    40960
#define OFF_B1    57344
#define SMEM_TOTAL 73728

// ---------------- kernel 1: L2-normalize rows (fp16 out) + allones flag ----------------
__global__ void k_norm(const float* __restrict__ zf, const float* __restrict__ attr) {
    int row = blockIdx.x;
    int tid = threadIdx.x;           // 256 = DK
    float v = zf[row * DK + tid];
    float ss = v * v;
    #pragma unroll
    for (int o = 16; o; o >>= 1) ss += __shfl_xor_sync(0xffffffffu, ss, o);
    __shared__ float ws[8];
    __shared__ float s_inv;
    if ((tid & 31) == 0) ws[tid >> 5] = ss;
    __syncthreads();
    if (tid == 0) {
        float t = 0.f;
        #pragma unroll
        for (int i = 0; i < 8; i++) t += ws[i];
        s_inv = 1.0f / fmaxf(sqrtf(t), 1e-12f);
        const float* a = attr + row * 4;
        g_ao[row] = ((a[0] + a[1] + a[2] + a[3]) == 4.0f) ? 1 : 0;
    }
    __syncthreads();
    g_znh[row * DK + tid] = __float2half(v * s_inv);
}

// ---- chunk loader: one K-chunk (64 halves = 128 B/row) of A and B panels ----
__device__ __forceinline__ void load_chunk(uint32_t sbase, uint32_t offA, uint32_t offB,
                                           int i0, int j0, int kc, int tid) {
    #pragma unroll
    for (int u = 0; u < 4; u++) {
        int idx = tid + 256 * u;          // 0..1023
        int r = idx >> 3;                 // row 0..127
        int c = idx & 7;                  // 16B chunk within 128B row
        int phys = (c ^ r) & 7;
        cp16(sbase + offA + r * 128 + phys * 16, &g_znh[(i0 + r) * DK + kc * 64 + c * 8]);
        cp16(sbase + offB + r * 128 + phys * 16, &g_znh[(j0 + r) * DK + kc * 64 + c * 8]);
    }
    CP_COMMIT();
}

// ---- chunk compute: 4 k-steps of 16 halves over one buffered chunk ----
__device__ __forceinline__ void compute_chunk(uint32_t sbase, uint32_t offA, uint32_t offB,
                                              int wr, int wc, int lane,
                                              float (&acc)[4][4][4]) {
    #pragma unroll
    for (int kk = 0; kk < 4; kk++) {
        uint32_t afr[4][4], bfr[2][4];
        const int cch = kk * 2 + (lane >> 4);      // 16B chunk 0..7
        #pragma unroll
        for (int mi = 0; mi < 4; mi++) {
            int r = wr * 64 + mi * 16 + (lane & 15);
            int phys = (cch ^ r) & 7;
            ldsm_x4(afr[mi][0], afr[mi][1], afr[mi][2], afr[mi][3],
                    sbase + offA + r * 128 + phys * 16);
        }
        #pragma unroll
        for (int n2 = 0; n2 < 2; n2++) {
            int r = wc * 32 + n2 * 16 + (lane & 15);
            int phys = (cch ^ r) & 7;
            ldsm_x4(bfr[n2][0], bfr[n2][1], bfr[n2][2], bfr[n2][3],
                    sbase + offB + r * 128 + phys * 16);
        }
        #pragma unroll
        for (int mi = 0; mi < 4; mi++)
            #pragma unroll
            for (int ni = 0; ni < 4; ni++) {
                int n2 = ni >> 1, odd = ni & 1;
                mma16816(acc[mi][ni], afr[mi], bfr[n2][odd], bfr[n2][odd + 2]);
            }
    }
}

// ---------------- kernel 2: HMMA gram tile, cp.async double-buffered ----------------
__global__ __launch_bounds__(256) void k_gram_mma() {
    extern __shared__ char smem[];
    const int it = blockIdx.x, jt = blockIdx.y;
    if (jt < it) return;

    const uint32_t sbase = smem_u32(smem);
    const int tid = threadIdx.x;
    const int wid = tid >> 5;
    const int lane = tid & 31;
    const int wr = wid & 1;
    const int wc = wid >> 1;
    const int i0 = it * 128, j0 = jt * 128;

    if (tid < 128) smem[OFF_AOI + tid] = (char)g_ao[i0 + tid];
    else           smem[OFF_AOJ + tid - 128] = (char)g_ao[j0 + (tid - 128)];

    float acc[4][4][4];
    #pragma unroll
    for (int mi = 0; mi < 4; mi++)
        #pragma unroll
        for (int ni = 0; ni < 4; ni++)
            #pragma unroll
            for (int e = 0; e < 4; e++) acc[mi][ni][e] = 0.f;

    // software pipeline: prefetch chunks 0,1; compute/load overlapped
    load_chunk(sbase, OFF_A0, OFF_B0, i0, j0, 0, tid);
    load_chunk(sbase, OFF_A1, OFF_B1, i0, j0, 1, tid);

    CP_WAIT(1); __syncthreads();
    compute_chunk(sbase, OFF_A0, OFF_B0, wr, wc, lane, acc);
    __syncthreads();
    load_chunk(sbase, OFF_A0, OFF_B0, i0, j0, 2, tid);

    CP_WAIT(1); __syncthreads();
    compute_chunk(sbase, OFF_A1, OFF_B1, wr, wc, lane, acc);
    __syncthreads();
    load_chunk(sbase, OFF_A1, OFF_B1, i0, j0, 3, tid);

    CP_WAIT(1); __syncthreads();
    compute_chunk(sbase, OFF_A0, OFF_B0, wr, wc, lane, acc);

    CP_WAIT(0); __syncthreads();
    compute_chunk(sbase, OFF_A1, OFF_B1, wr, wc, lane, acc);

    // ---- epilogue: exp + per-thread row/col partial sums ----
    const int g = lane >> 2;
    const int cp2 = (lane & 3) * 2;
    float rs[8], rp[8], cs[8], cpn[8];
    #pragma unroll
    for (int x = 0; x < 8; x++) { rs[x] = rp[x] = cs[x] = cpn[x] = 0.f; }

    const bool diag = (it == jt);
    #pragma unroll
    for (int mi = 0; mi < 4; mi++) {
        #pragma unroll
        for (int h = 0; h < 2; h++) {
            int rloc = wr * 64 + mi * 16 + h * 8 + g;
            bool aoi_r = smem[OFF_AOI + rloc] != 0;
            #pragma unroll
            for (int ni = 0; ni < 4; ni++) {
                #pragma unroll
                for (int q = 0; q < 2; q++) {
                    int cloc = wc * 32 + ni * 8 + cp2 + q;
                    float e = __expf(acc[mi][ni][h * 2 + q] * TEMP_INV);
                    if (diag && rloc == cloc) e = 0.f;
                    rs[mi * 2 + h] += e;
                    if (smem[OFF_AOJ + cloc]) rp[mi * 2 + h] += e;
                    cs[ni * 2 + q] += e;
                    if (aoi_r) cpn[ni * 2 + q] += e;
                }
            }
        }
    }

    #pragma unroll
    for (int x = 0; x < 8; x++) {
        rs[x] += __shfl_xor_sync(0xffffffffu, rs[x], 1);
        rs[x] += __shfl_xor_sync(0xffffffffu, rs[x], 2);
        rp[x] += __shfl_xor_sync(0xffffffffu, rp[x], 1);
        rp[x] += __shfl_xor_sync(0xffffffffu, rp[x], 2);
    }
    float* rpa = reinterpret_cast<float*>(smem + OFF_RPA);
    float* rpp = reinterpret_cast<float*>(smem + OFF_RPP);
    if ((lane & 3) == 0) {
        #pragma unroll
        for (int mi = 0; mi < 4; mi++)
            #pragma unroll
            for (int h = 0; h < 2; h++) {
                int rloc = wr * 64 + mi * 16 + h * 8 + g;
                rpa[wc * 128 + rloc] = rs[mi * 2 + h];
                rpp[wc * 128 + rloc] = rp[mi * 2 + h];
            }
    }

    #pragma unroll
    for (int x = 0; x < 8; x++) {
        cs[x] += __shfl_xor_sync(0xffffffffu, cs[x], 4);
        cs[x] += __shfl_xor_sync(0xffffffffu, cs[x], 8);
        cs[x] += __shfl_xor_sync(0xffffffffu, cs[x], 16);
        cpn[x] += __shfl_xor_sync(0xffffffffu, cpn[x], 4);
        cpn[x] += __shfl_xor_sync(0xffffffffu, cpn[x], 8);
        cpn[x] += __shfl_xor_sync(0xffffffffu, cpn[x], 16);
    }
    float* cpa = reinterpret_cast<float*>(smem + OFF_CPA);
    float* cpp = reinterpret_cast<float*>(smem + OFF_CPP);
    if (lane < 4) {
        #pragma unroll
        for (int ni = 0; ni < 4; ni++)
            #pragma unroll
            for (int q = 0; q < 2; q++) {
                int cloc = wc * 32 + ni * 8 + lane * 2 + q;
                cpa[wr * 128 + cloc] = cs[ni * 2 + q];
                cpp[wr * 128 + cloc] = cpn[ni * 2 + q];
            }
    }
    __syncthreads();

    if (tid < 128) {
        float a = rpa[tid] + rpa[128 + tid] + rpa[256 + tid] + rpa[384 + tid];
        float p = rpp[tid] + rpp[128 + tid] + rpp[256 + tid] + rpp[384 + tid];
        g_pall[jt * BN + i0 + tid] = a;
        g_ppos[jt * BN + i0 + tid] = (smem[OFF_AOI + tid] != 0) ? p : 0.f;
    } else if (it != jt) {
        int j = tid - 128;
        float a = cpa[j] + cpa[128 + j];
        float p = cpp[j] + cpp[128 + j];
        g_pall[it * BN + j0 + j] = a;
        g_ppos[it * BN + j0 + j] = (smem[OFF_AOJ + j] != 0) ? p : 0.f;
    }
}

// ---------------- kernel 3: per-row loss + last-block final reduction ----------------
__global__ void k_rowloss_final(float* __restrict__ out) {
    int i = blockIdx.x * blockDim.x + threadIdx.x;
    float all = 0.f, pos = 0.f;
    #pragma unroll 4
    for (int t = 0; t < NTILES; t++) {
        all += g_pall[t * BN + i];
        pos += g_ppos[t * BN + i];
    }
    bool valid = (g_ao[i] != 0) && (pos > 0.f);
    float loss = valid ? (logf(all) - logf(pos)) : 0.f;
    unsigned int cnt = valid ? 1u : 0u;
    #pragma unroll
    for (int o = 16; o; o >>= 1) {
        loss += __shfl_xor_sync(0xffffffffu, loss, o);
        cnt  += __shfl_xor_sync(0xffffffffu, cnt, o);
    }
    __shared__ float ws[8];
    __shared__ unsigned int wcv[8];
    __shared__ bool s_last;
    int tid = threadIdx.x;
    if ((tid & 31) == 0) { ws[tid >> 5] = loss; wcv[tid >> 5] = cnt; }
    __syncthreads();
    if (tid == 0) {
        float s = 0.f; unsigned int c = 0u;
        #pragma unroll
        for (int k = 0; k < 8; k++) { s += ws[k]; c += wcv[k]; }
        g_blocksum[blockIdx.x] = s;
        g_blockcnt[blockIdx.x] = c;
        __threadfence();
        unsigned int t = atomicAdd(&g_ticket, 1u);
        s_last = (t == gridDim.x - 1);
    }
    __syncthreads();
    if (s_last && tid < 32) {
        float s = g_blocksum[tid];
        unsigned int c = g_blockcnt[tid];
        #pragma unroll
        for (int o = 16; o; o >>= 1) {
            s += __shfl_xor_sync(0xffffffffu, s, o);
            c += __shfl_xor_sync(0xffffffffu, c, o);
        }
        if (tid == 0) {
            out[0] = (c > 0u) ? (s / (float)c) : 0.f;
            g_ticket = 0;   // reset for next (graph-replayed) call
        }
    }
}

// ---------------- entry point ----------------
extern "C" void kernel_launch(void* const* d_in, const int* in_sizes, int n_in,
                              void* d_out, int out_size) {
    const float* zf   = (const float*)d_in[1];
    const float* attr = (const float*)d_in[2];
    float* out = (float*)d_out;

    cudaFuncSetAttribute(k_gram_mma, cudaFuncAttributeMaxDynamicSharedMemorySize, SMEM_TOTAL);

    k_norm<<<BN, DK>>>(zf, attr);
    k_gram_mma<<<dim3(NTILES, NTILES), 256, SMEM_TOTAL>>>();
    k_rowloss_final<<<BN / 256, 256>>>(out);
}

// round 11
// speedup vs baseline: 9.9245x; 1.0768x over previous
#include <cuda_runtime.h>
#include <cuda_fp16.h>
#include <math.h>
#include <stdint.h>

#define BN 8192
#define DK 256
#define NTILES 64
#define NPAIRS 2080                     // NTILES*(NTILES+1)/2
#define TEMP_INV 14.2857142857142857f   // 1/0.07

// ---------------- static device scratch ----------------
__device__ __align__(16) __half g_znh[BN * DK];   // fp16 normalized z_flowed (4 MB)
__device__ unsigned char g_ao[BN];                // allones flag per row
__device__ float g_pall[NTILES * BN];             // partial all-sums  [colTile][row]
__device__ float g_ppos[NTILES * BN];             // partial pos-sums  [colTile][row]
__device__ float g_blocksum[32];
__device__ unsigned int g_blockcnt[32];
__device__ unsigned int g_ticket;                 // zero-init; self-resetting

__device__ __forceinline__ uint32_t smem_u32(const void* p) {
    uint32_t a;
    asm("{ .reg .u64 t; cvta.to.shared.u64 t, %1; cvt.u32.u64 %0, t; }" : "=r"(a) : "l"(p));
    return a;
}
__device__ __forceinline__ void ldsm_x4(uint32_t& r0, uint32_t& r1, uint32_t& r2, uint32_t& r3,
                                        uint32_t addr) {
    asm volatile("ldmatrix.sync.aligned.m8n8.x4.shared.b16 {%0,%1,%2,%3}, [%4];"
                 : "=r"(r0), "=r"(r1), "=r"(r2), "=r"(r3) : "r"(addr));
}
__device__ __forceinline__ void mma16816(float* d, const uint32_t* a, uint32_t b0, uint32_t b1) {
    asm volatile(
        "mma.sync.aligned.m16n8k16.row.col.f32.f16.f16.f32 "
        "{%0,%1,%2,%3}, {%4,%5,%6,%7}, {%8,%9}, {%0,%1,%2,%3};"
        : "+f"(d[0]), "+f"(d[1]), "+f"(d[2]), "+f"(d[3])
        : "r"(a[0]), "r"(a[1]), "r"(a[2]), "r"(a[3]), "r"(b0), "r"(b1));
}
__device__ __forceinline__ void cp16(uint32_t dst, const void* src) {
    asm volatile("cp.async.cg.shared.global [%0], [%1], 16;" :: "r"(dst), "l"(src) : "memory");
}
#define CP_COMMIT() asm volatile("cp.async.commit_group;" ::: "memory")
#define CP_WAIT(n)  asm volatile("cp.async.wait_group %0;" :: "n"(n) : "memory")

// smem layout (dynamic)
#define OFF_AOI   0
#define OFF_AOJ   128
#define OFF_RPA   256
#define OFF_RPP   2304
#define OFF_CPA   4352
#define OFF_CPP   5376
#define OFF_A0    8192
#define OFF_B0    24576
#define OFF_A1    40960
#define OFF_B1    57344
#define SMEM_TOTAL 73728

// ---------------- kernel 1: warp-per-row L2-normalize (fp16 out) + allones ----------------
__global__ void k_norm(const float* __restrict__ zf, const float* __restrict__ attr) {
    const int row = blockIdx.x * 8 + (threadIdx.x >> 5);
    const int lane = threadIdx.x & 31;
    const float4* src = reinterpret_cast<const float4*>(zf + row * DK);
    float4 v0 = src[lane * 2];
    float4 v1 = src[lane * 2 + 1];
    float ss = v0.x * v0.x + v0.y * v0.y + v0.z * v0.z + v0.w * v0.w
             + v1.x * v1.x + v1.y * v1.y + v1.z * v1.z + v1.w * v1.w;
    #pragma unroll
    for (int o = 16; o; o >>= 1) ss += __shfl_xor_sync(0xffffffffu, ss, o);
    float inv = 1.0f / fmaxf(sqrtf(ss), 1e-12f);

    __half2 h[4];
    h[0] = __floats2half2_rn(v0.x * inv, v0.y * inv);
    h[1] = __floats2half2_rn(v0.z * inv, v0.w * inv);
    h[2] = __floats2half2_rn(v1.x * inv, v1.y * inv);
    h[3] = __floats2half2_rn(v1.z * inv, v1.w * inv);
    *reinterpret_cast<uint4*>(&g_znh[row * DK + lane * 8]) = *reinterpret_cast<uint4*>(h);

    if (lane == 0) {
        const float* a = attr + row * 4;
        g_ao[row] = ((a[0] + a[1] + a[2] + a[3]) == 4.0f) ? 1 : 0;
    }
}

// ---- chunk loader: one K-chunk (64 halves = 128 B/row) of A and B panels ----
__device__ __forceinline__ void load_chunk(uint32_t sbase, uint32_t offA, uint32_t offB,
                                           int i0, int j0, int kc, int tid) {
    #pragma unroll
    for (int u = 0; u < 4; u++) {
        int idx = tid + 256 * u;
        int r = idx >> 3;
        int c = idx & 7;
        int phys = (c ^ r) & 7;
        cp16(sbase + offA + r * 128 + phys * 16, &g_znh[(i0 + r) * DK + kc * 64 + c * 8]);
        cp16(sbase + offB + r * 128 + phys * 16, &g_znh[(j0 + r) * DK + kc * 64 + c * 8]);
    }
    CP_COMMIT();
}

// ---- chunk compute: 4 k-steps of 16 halves over one buffered chunk ----
__device__ __forceinline__ void compute_chunk(uint32_t sbase, uint32_t offA, uint32_t offB,
                                              int wr, int wc, int lane,
                                              float (&acc)[4][4][4]) {
    #pragma unroll
    for (int kk = 0; kk < 4; kk++) {
        uint32_t afr[4][4], bfr[2][4];
        const int cch = kk * 2 + (lane >> 4);
        #pragma unroll
        for (int mi = 0; mi < 4; mi++) {
            int r = wr * 64 + mi * 16 + (lane & 15);
            int phys = (cch ^ r) & 7;
            ldsm_x4(afr[mi][0], afr[mi][1], afr[mi][2], afr[mi][3],
                    sbase + offA + r * 128 + phys * 16);
        }
        #pragma unroll
        for (int n2 = 0; n2 < 2; n2++) {
            int r = wc * 32 + n2 * 16 + (lane & 15);
            int phys = (cch ^ r) & 7;
            ldsm_x4(bfr[n2][0], bfr[n2][1], bfr[n2][2], bfr[n2][3],
                    sbase + offB + r * 128 + phys * 16);
        }
        #pragma unroll
        for (int mi = 0; mi < 4; mi++)
            #pragma unroll
            for (int ni = 0; ni < 4; ni++) {
                int n2 = ni >> 1, odd = ni & 1;
                mma16816(acc[mi][ni], afr[mi], bfr[n2][odd], bfr[n2][odd + 2]);
            }
    }
}

// ---------------- kernel 2: HMMA gram tile, triangular linear grid ----------------
__global__ __launch_bounds__(256) void k_gram_mma() {
    extern __shared__ char smem[];
    // decode linear pair index -> (it <= jt)
    const int t = blockIdx.x;
    int jt = (int)((sqrtf(8.0f * t + 1.0f) - 1.0f) * 0.5f);
    while ((jt + 1) * (jt + 2) / 2 <= t) jt++;
    while (jt * (jt + 1) / 2 > t) jt--;
    const int it = t - jt * (jt + 1) / 2;

    const uint32_t sbase = smem_u32(smem);
    const int tid = threadIdx.x;
    const int wid = tid >> 5;
    const int lane = tid & 31;
    const int wr = wid & 1;
    const int wc = wid >> 1;
    const int i0 = it * 128, j0 = jt * 128;

    if (tid < 128) smem[OFF_AOI + tid] = (char)g_ao[i0 + tid];
    else           smem[OFF_AOJ + tid - 128] = (char)g_ao[j0 + (tid - 128)];

    float acc[4][4][4];
    #pragma unroll
    for (int mi = 0; mi < 4; mi++)
        #pragma unroll
        for (int ni = 0; ni < 4; ni++)
            #pragma unroll
            for (int e = 0; e < 4; e++) acc[mi][ni][e] = 0.f;

    load_chunk(sbase, OFF_A0, OFF_B0, i0, j0, 0, tid);
    load_chunk(sbase, OFF_A1, OFF_B1, i0, j0, 1, tid);

    CP_WAIT(1); __syncthreads();
    compute_chunk(sbase, OFF_A0, OFF_B0, wr, wc, lane, acc);
    __syncthreads();
    load_chunk(sbase, OFF_A0, OFF_B0, i0, j0, 2, tid);

    CP_WAIT(1); __syncthreads();
    compute_chunk(sbase, OFF_A1, OFF_B1, wr, wc, lane, acc);
    __syncthreads();
    load_chunk(sbase, OFF_A1, OFF_B1, i0, j0, 3, tid);

    CP_WAIT(1); __syncthreads();
    compute_chunk(sbase, OFF_A0, OFF_B0, wr, wc, lane, acc);

    CP_WAIT(0); __syncthreads();
    compute_chunk(sbase, OFF_A1, OFF_B1, wr, wc, lane, acc);

    // ---- epilogue: exp + per-thread row/col partial sums ----
    const int g = lane >> 2;
    const int cp2 = (lane & 3) * 2;
    float rs[8], rp[8], cs[8], cpn[8];
    #pragma unroll
    for (int x = 0; x < 8; x++) { rs[x] = rp[x] = cs[x] = cpn[x] = 0.f; }

    const bool diag = (it == jt);
    #pragma unroll
    for (int mi = 0; mi < 4; mi++) {
        #pragma unroll
        for (int h = 0; h < 2; h++) {
            int rloc = wr * 64 + mi * 16 + h * 8 + g;
            bool aoi_r = smem[OFF_AOI + rloc] != 0;
            #pragma unroll
            for (int ni = 0; ni < 4; ni++) {
                #pragma unroll
                for (int q = 0; q < 2; q++) {
                    int cloc = wc * 32 + ni * 8 + cp2 + q;
                    float e = __expf(acc[mi][ni][h * 2 + q] * TEMP_INV);
                    if (diag && rloc == cloc) e = 0.f;
                    rs[mi * 2 + h] += e;
                    if (smem[OFF_AOJ + cloc]) rp[mi * 2 + h] += e;
                    cs[ni * 2 + q] += e;
                    if (aoi_r) cpn[ni * 2 + q] += e;
                }
            }
        }
    }

    #pragma unroll
    for (int x = 0; x < 8; x++) {
        rs[x] += __shfl_xor_sync(0xffffffffu, rs[x], 1);
        rs[x] += __shfl_xor_sync(0xffffffffu, rs[x], 2);
        rp[x] += __shfl_xor_sync(0xffffffffu, rp[x], 1);
        rp[x] += __shfl_xor_sync(0xffffffffu, rp[x], 2);
    }
    float* rpa = reinterpret_cast<float*>(smem + OFF_RPA);
    float* rpp = reinterpret_cast<float*>(smem + OFF_RPP);
    if ((lane & 3) == 0) {
        #pragma unroll
        for (int mi = 0; mi < 4; mi++)
            #pragma unroll
            for (int h = 0; h < 2; h++) {
                int rloc = wr * 64 + mi * 16 + h * 8 + g;
                rpa[wc * 128 + rloc] = rs[mi * 2 + h];
                rpp[wc * 128 + rloc] = rp[mi * 2 + h];
            }
    }

    #pragma unroll
    for (int x = 0; x < 8; x++) {
        cs[x] += __shfl_xor_sync(0xffffffffu, cs[x], 4);
        cs[x] += __shfl_xor_sync(0xffffffffu, cs[x], 8);
        cs[x] += __shfl_xor_sync(0xffffffffu, cs[x], 16);
        cpn[x] += __shfl_xor_sync(0xffffffffu, cpn[x], 4);
        cpn[x] += __shfl_xor_sync(0xffffffffu, cpn[x], 8);
        cpn[x] += __shfl_xor_sync(0xffffffffu, cpn[x], 16);
    }
    float* cpa = reinterpret_cast<float*>(smem + OFF_CPA);
    float* cpp = reinterpret_cast<float*>(smem + OFF_CPP);
    if (lane < 4) {
        #pragma unroll
        for (int ni = 0; ni < 4; ni++)
            #pragma unroll
            for (int q = 0; q < 2; q++) {
                int cloc = wc * 32 + ni * 8 + lane * 2 + q;
                cpa[wr * 128 + cloc] = cs[ni * 2 + q];
                cpp[wr * 128 + cloc] = cpn[ni * 2 + q];
            }
    }
    __syncthreads();

    if (tid < 128) {
        float a = rpa[tid] + rpa[128 + tid] + rpa[256 + tid] + rpa[384 + tid];
        float p = rpp[tid] + rpp[128 + tid] + rpp[256 + tid] + rpp[384 + tid];
        g_pall[jt * BN + i0 + tid] = a;
        g_ppos[jt * BN + i0 + tid] = (smem[OFF_AOI + tid] != 0) ? p : 0.f;
    } else if (it != jt) {
        int j = tid - 128;
        float a = cpa[j] + cpa[128 + j];
        float p = cpp[j] + cpp[128 + j];
        g_pall[it * BN + j0 + j] = a;
        g_ppos[it * BN + j0 + j] = (smem[OFF_AOJ + j] != 0) ? p : 0.f;
    }
}

// ---------------- kernel 3: per-row loss + last-block final reduction ----------------
__global__ void k_rowloss_final(float* __restrict__ out) {
    int i = blockIdx.x * blockDim.x + threadIdx.x;
    float all = 0.f, pos = 0.f;
    #pragma unroll 4
    for (int t = 0; t < NTILES; t++) {
        all += g_pall[t * BN + i];
        pos += g_ppos[t * BN + i];
    }
    bool valid = (g_ao[i] != 0) && (pos > 0.f);
    float loss = valid ? (logf(all) - logf(pos)) : 0.f;
    unsigned int cnt = valid ? 1u : 0u;
    #pragma unroll
    for (int o = 16; o; o >>= 1) {
        loss += __shfl_xor_sync(0xffffffffu, loss, o);
        cnt  += __shfl_xor_sync(0xffffffffu, cnt, o);
    }
    __shared__ float ws[8];
    __shared__ unsigned int wcv[8];
    __shared__ bool s_last;
    int tid = threadIdx.x;
    if ((tid & 31) == 0) { ws[tid >> 5] = loss; wcv[tid >> 5] = cnt; }
    __syncthreads();
    if (tid == 0) {
        float s = 0.f; unsigned int c = 0u;
        #pragma unroll
        for (int k = 0; k < 8; k++) { s += ws[k]; c += wcv[k]; }
        g_blocksum[blockIdx.x] = s;
        g_blockcnt[blockIdx.x] = c;
        __threadfence();
        unsigned int t = atomicAdd(&g_ticket, 1u);
        s_last = (t == gridDim.x - 1);
    }
    __syncthreads();
    if (s_last && tid < 32) {
        float s = g_blocksum[tid];
        unsigned int c = g_blockcnt[tid];
        #pragma unroll
        for (int o = 16; o; o >>= 1) {
            s += __shfl_xor_sync(0xffffffffu, s, o);
            c += __shfl_xor_sync(0xffffffffu, c, o);
        }
        if (tid == 0) {
            out[0] = (c > 0u) ? (s / (float)c) : 0.f;
            g_ticket = 0;   // reset for next graph replay
        }
    }
}

// ---------------- entry point ----------------
extern "C" void kernel_launch(void* const* d_in, const int* in_sizes, int n_in,
                              void* d_out, int out_size) {
    const float* zf   = (const float*)d_in[1];
    const float* attr = (const float*)d_in[2];
    float* out = (float*)d_out;

    cudaFuncSetAttribute(k_gram_mma, cudaFuncAttributeMaxDynamicSharedMemorySize, SMEM_TOTAL);

    k_norm<<<BN / 8, 256>>>(zf, attr);
    k_gram_mma<<<NPAIRS, 256, SMEM_TOTAL>>>();
    k_rowloss_final<<<BN / 256, 256>>>(out);
}

// round 12
// speedup vs baseline: 10.2545x; 1.0333x over previous
#include <cuda_runtime.h>
#include <cuda_fp16.h>
#include <math.h>
#include <stdint.h>

#define BN 8192
#define DK 256
#define NTILES 64
#define NPAIRS 2080                     // NTILES*(NTILES+1)/2
#define TEMP_INV 14.2857142857142857f   // 1/0.07

// ---------------- static device scratch ----------------
__device__ __align__(16) __half g_znh[BN * DK];   // fp16 normalized z_flowed (4 MB)
__device__ unsigned char g_ao[BN];                // allones flag per row
__device__ float g_pall[NTILES * BN];             // partial all-sums  [colTile][row]
__device__ float g_ppos[NTILES * BN];             // partial pos-sums  [colTile][row]
__device__ float g_blocksum[32];
__device__ unsigned int g_blockcnt[32];
__device__ unsigned int g_ticket;                 // zero-init; self-resetting

__device__ __forceinline__ uint32_t smem_u32(const void* p) {
    uint32_t a;
    asm("{ .reg .u64 t; cvta.to.shared.u64 t, %1; cvt.u32.u64 %0, t; }" : "=r"(a) : "l"(p));
    return a;
}
__device__ __forceinline__ void ldsm_x4(uint32_t& r0, uint32_t& r1, uint32_t& r2, uint32_t& r3,
                                        uint32_t addr) {
    asm volatile("ldmatrix.sync.aligned.m8n8.x4.shared.b16 {%0,%1,%2,%3}, [%4];"
                 : "=r"(r0), "=r"(r1), "=r"(r2), "=r"(r3) : "r"(addr));
}
// full-rate f16-accumulator HMMA: C/D are 2 regs of f16x2
__device__ __forceinline__ void mma16816_f16(uint32_t* d, const uint32_t* a,
                                             uint32_t b0, uint32_t b1) {
    asm volatile(
        "mma.sync.aligned.m16n8k16.row.col.f16.f16.f16.f16 "
        "{%0,%1}, {%2,%3,%4,%5}, {%6,%7}, {%0,%1};"
        : "+r"(d[0]), "+r"(d[1])
        : "r"(a[0]), "r"(a[1]), "r"(a[2]), "r"(a[3]), "r"(b0), "r"(b1));
}
__device__ __forceinline__ void cp16(uint32_t dst, const void* src) {
    asm volatile("cp.async.cg.shared.global [%0], [%1], 16;" :: "r"(dst), "l"(src) : "memory");
}
#define CP_COMMIT() asm volatile("cp.async.commit_group;" ::: "memory")
#define CP_WAIT(n)  asm volatile("cp.async.wait_group %0;" :: "n"(n) : "memory")

// smem layout (dynamic)
#define OFF_AOI   0
#define OFF_AOJ   128
#define OFF_RPA   256
#define OFF_RPP   2304
#define OFF_CPA   4352
#define OFF_CPP   5376
#define OFF_A0    8192
#define OFF_B0    24576
#define OFF_A1    40960
#define OFF_B1    57344
#define SMEM_TOTAL 73728

// ---------------- kernel 1: warp-per-row L2-normalize (fp16 out) + allones ----------------
__global__ void k_norm(const float* __restrict__ zf, const float* __restrict__ attr) {
    const int row = blockIdx.x * 8 + (threadIdx.x >> 5);
    const int lane = threadIdx.x & 31;
    const float4* src = reinterpret_cast<const float4*>(zf + row * DK);
    float4 v0 = src[lane * 2];
    float4 v1 = src[lane * 2 + 1];
    float ss = v0.x * v0.x + v0.y * v0.y + v0.z * v0.z + v0.w * v0.w
             + v1.x * v1.x + v1.y * v1.y + v1.z * v1.z + v1.w * v1.w;
    #pragma unroll
    for (int o = 16; o; o >>= 1) ss += __shfl_xor_sync(0xffffffffu, ss, o);
    float inv = 1.0f / fmaxf(sqrtf(ss), 1e-12f);

    __half2 h[4];
    h[0] = __floats2half2_rn(v0.x * inv, v0.y * inv);
    h[1] = __floats2half2_rn(v0.z * inv, v0.w * inv);
    h[2] = __floats2half2_rn(v1.x * inv, v1.y * inv);
    h[3] = __floats2half2_rn(v1.z * inv, v1.w * inv);
    *reinterpret_cast<uint4*>(&g_znh[row * DK + lane * 8]) = *reinterpret_cast<uint4*>(h);

    if (lane == 0) {
        const float* a = attr + row * 4;
        g_ao[row] = ((a[0] + a[1] + a[2] + a[3]) == 4.0f) ? 1 : 0;
    }
}

// ---- chunk loader: one K-chunk (64 halves = 128 B/row) of A and B panels ----
__device__ __forceinline__ void load_chunk(uint32_t sbase, uint32_t offA, uint32_t offB,
                                           int i0, int j0, int kc, int tid) {
    #pragma unroll
    for (int u = 0; u < 4; u++) {
        int idx = tid + 256 * u;
        int r = idx >> 3;
        int c = idx & 7;
        int phys = (c ^ r) & 7;
        cp16(sbase + offA + r * 128 + phys * 16, &g_znh[(i0 + r) * DK + kc * 64 + c * 8]);
        cp16(sbase + offB + r * 128 + phys * 16, &g_znh[(j0 + r) * DK + kc * 64 + c * 8]);
    }
    CP_COMMIT();
}

// ---- chunk compute: 4 k-steps of 16 halves over one buffered chunk (f16 acc) ----
__device__ __forceinline__ void compute_chunk(uint32_t sbase, uint32_t offA, uint32_t offB,
                                              int wr, int wc, int lane,
                                              uint32_t (&acc)[4][4][2]) {
    #pragma unroll
    for (int kk = 0; kk < 4; kk++) {
        uint32_t afr[4][4], bfr[2][4];
        const int cch = kk * 2 + (lane >> 4);
        #pragma unroll
        for (int mi = 0; mi < 4; mi++) {
            int r = wr * 64 + mi * 16 + (lane & 15);
            int phys = (cch ^ r) & 7;
            ldsm_x4(afr[mi][0], afr[mi][1], afr[mi][2], afr[mi][3],
                    sbase + offA + r * 128 + phys * 16);
        }
        #pragma unroll
        for (int n2 = 0; n2 < 2; n2++) {
            int r = wc * 32 + n2 * 16 + (lane & 15);
            int phys = (cch ^ r) & 7;
            ldsm_x4(bfr[n2][0], bfr[n2][1], bfr[n2][2], bfr[n2][3],
                    sbase + offB + r * 128 + phys * 16);
        }
        #pragma unroll
        for (int mi = 0; mi < 4; mi++)
            #pragma unroll
            for (int ni = 0; ni < 4; ni++) {
                int n2 = ni >> 1, odd = ni & 1;
                mma16816_f16(acc[mi][ni], afr[mi], bfr[n2][odd], bfr[n2][odd + 2]);
            }
    }
}

// ---------------- kernel 2: HMMA gram tile, triangular linear grid, 2 blocks/SM ----------------
__global__ __launch_bounds__(256, 2) void k_gram_mma() {
    extern __shared__ char smem[];
    const int t = blockIdx.x;
    int jt = (int)((sqrtf(8.0f * t + 1.0f) - 1.0f) * 0.5f);
    while ((jt + 1) * (jt + 2) / 2 <= t) jt++;
    while (jt * (jt + 1) / 2 > t) jt--;
    const int it = t - jt * (jt + 1) / 2;

    const uint32_t sbase = smem_u32(smem);
    const int tid = threadIdx.x;
    const int wid = tid >> 5;
    const int lane = tid & 31;
    const int wr = wid & 1;
    const int wc = wid >> 1;
    const int i0 = it * 128, j0 = jt * 128;

    if (tid < 128) smem[OFF_AOI + tid] = (char)g_ao[i0 + tid];
    else           smem[OFF_AOJ + tid - 128] = (char)g_ao[j0 + (tid - 128)];

    uint32_t acc[4][4][2];
    #pragma unroll
    for (int mi = 0; mi < 4; mi++)
        #pragma unroll
        for (int ni = 0; ni < 4; ni++) { acc[mi][ni][0] = 0u; acc[mi][ni][1] = 0u; }

    load_chunk(sbase, OFF_A0, OFF_B0, i0, j0, 0, tid);
    load_chunk(sbase, OFF_A1, OFF_B1, i0, j0, 1, tid);

    CP_WAIT(1); __syncthreads();
    compute_chunk(sbase, OFF_A0, OFF_B0, wr, wc, lane, acc);
    __syncthreads();
    load_chunk(sbase, OFF_A0, OFF_B0, i0, j0, 2, tid);

    CP_WAIT(1); __syncthreads();
    compute_chunk(sbase, OFF_A1, OFF_B1, wr, wc, lane, acc);
    __syncthreads();
    load_chunk(sbase, OFF_A1, OFF_B1, i0, j0, 3, tid);

    CP_WAIT(1); __syncthreads();
    compute_chunk(sbase, OFF_A0, OFF_B0, wr, wc, lane, acc);

    CP_WAIT(0); __syncthreads();
    compute_chunk(sbase, OFF_A1, OFF_B1, wr, wc, lane, acc);

    // ---- epilogue: exp + per-thread row/col partial sums ----
    const int g = lane >> 2;
    const int cp2 = (lane & 3) * 2;
    float rs[8], rp[8], cs[8], cpn[8];
    #pragma unroll
    for (int x = 0; x < 8; x++) { rs[x] = rp[x] = cs[x] = cpn[x] = 0.f; }

    const bool diag = (it == jt);
    #pragma unroll
    for (int mi = 0; mi < 4; mi++) {
        #pragma unroll
        for (int h = 0; h < 2; h++) {
            int rloc = wr * 64 + mi * 16 + h * 8 + g;
            bool aoi_r = smem[OFF_AOI + rloc] != 0;
            #pragma unroll
            for (int ni = 0; ni < 4; ni++) {
                float2 v = __half22float2(*reinterpret_cast<__half2*>(&acc[mi][ni][h]));
                #pragma unroll
                for (int q = 0; q < 2; q++) {
                    int cloc = wc * 32 + ni * 8 + cp2 + q;
                    float e = __expf((q ? v.y : v.x) * TEMP_INV);
                    if (diag && rloc == cloc) e = 0.f;
                    rs[mi * 2 + h] += e;
                    if (smem[OFF_AOJ + cloc]) rp[mi * 2 + h] += e;
                    cs[ni * 2 + q] += e;
                    if (aoi_r) cpn[ni * 2 + q] += e;
                }
            }
        }
    }

    #pragma unroll
    for (int x = 0; x < 8; x++) {
        rs[x] += __shfl_xor_sync(0xffffffffu, rs[x], 1);
        rs[x] += __shfl_xor_sync(0xffffffffu, rs[x], 2);
        rp[x] += __shfl_xor_sync(0xffffffffu, rp[x], 1);
        rp[x] += __shfl_xor_sync(0xffffffffu, rp[x], 2);
    }
    float* rpa = reinterpret_cast<float*>(smem + OFF_RPA);
    float* rpp = reinterpret_cast<float*>(smem + OFF_RPP);
    if ((lane & 3) == 0) {
        #pragma unroll
        for (int mi = 0; mi < 4; mi++)
            #pragma unroll
            for (int h = 0; h < 2; h++) {
                int rloc = wr * 64 + mi * 16 + h * 8 + g;
                rpa[wc * 128 + rloc] = rs[mi * 2 + h];
                rpp[wc * 128 + rloc] = rp[mi * 2 + h];
            }
    }

    #pragma unroll
    for (int x = 0; x < 8; x++) {
        cs[x] += __shfl_xor_sync(0xffffffffu, cs[x], 4);
        cs[x] += __shfl_xor_sync(0xffffffffu, cs[x], 8);
        cs[x] += __shfl_xor_sync(0xffffffffu, cs[x], 16);
        cpn[x] += __shfl_xor_sync(0xffffffffu, cpn[x], 4);
        cpn[x] += __shfl_xor_sync(0xffffffffu, cpn[x], 8);
        cpn[x] += __shfl_xor_sync(0xffffffffu, cpn[x], 16);
    }
    float* cpa = reinterpret_cast<float*>(smem + OFF_CPA);
    float* cpp = reinterpret_cast<float*>(smem + OFF_CPP);
    if (lane < 4) {
        #pragma unroll
        for (int ni = 0; ni < 4; ni++)
            #pragma unroll
            for (int q = 0; q < 2; q++) {
                int cloc = wc * 32 + ni * 8 + lane * 2 + q;
                cpa[wr * 128 + cloc] = cs[ni * 2 + q];
                cpp[wr * 128 + cloc] = cpn[ni * 2 + q];
            }
    }
    __syncthreads();

    if (tid < 128) {
        float a = rpa[tid] + rpa[128 + tid] + rpa[256 + tid] + rpa[384 + tid];
        float p = rpp[tid] + rpp[128 + tid] + rpp[256 + tid] + rpp[384 + tid];
        g_pall[jt * BN + i0 + tid] = a;
        g_ppos[jt * BN + i0 + tid] = (smem[OFF_AOI + tid] != 0) ? p : 0.f;
    } else if (it != jt) {
        int j = tid - 128;
        float a = cpa[j] + cpa[128 + j];
        float p = cpp[j] + cpp[128 + j];
        g_pall[it * BN + j0 + j] = a;
        g_ppos[it * BN + j0 + j] = (smem[OFF_AOJ + j] != 0) ? p : 0.f;
    }
}

// ---------------- kernel 3: per-row loss + last-block final reduction ----------------
__global__ void k_rowloss_final(float* __restrict__ out) {
    int i = blockIdx.x * blockDim.x + threadIdx.x;
    float all = 0.f, pos = 0.f;
    #pragma unroll 4
    for (int t = 0; t < NTILES; t++) {
        all += g_pall[t * BN + i];
        pos += g_ppos[t * BN + i];
    }
    bool valid = (g_ao[i] != 0) && (pos > 0.f);
    float loss = valid ? (logf(all) - logf(pos)) : 0.f;
    unsigned int cnt = valid ? 1u : 0u;
    #pragma unroll
    for (int o = 16; o; o >>= 1) {
        loss += __shfl_xor_sync(0xffffffffu, loss, o);
        cnt  += __shfl_xor_sync(0xffffffffu, cnt, o);
    }
    __shared__ float ws[8];
    __shared__ unsigned int wcv[8];
    __shared__ bool s_last;
    int tid = threadIdx.x;
    if ((tid & 31) == 0) { ws[tid >> 5] = loss; wcv[tid >> 5] = cnt; }
    __syncthreads();
    if (tid == 0) {
        float s = 0.f; unsigned int c = 0u;
        #pragma unroll
        for (int k = 0; k < 8; k++) { s += ws[k]; c += wcv[k]; }
        g_blocksum[blockIdx.x] = s;
        g_blockcnt[blockIdx.x] = c;
        __threadfence();
        unsigned int t = atomicAdd(&g_ticket, 1u);
        s_last = (t == gridDim.x - 1);
    }
    __syncthreads();
    if (s_last && tid < 32) {
        float s = g_blocksum[tid];
        unsigned int c = g_blockcnt[tid];
        #pragma unroll
        for (int o = 16; o; o >>= 1) {
            s += __shfl_xor_sync(0xffffffffu, s, o);
            c += __shfl_xor_sync(0xffffffffu, c, o);
        }
        if (tid == 0) {
            out[0] = (c > 0u) ? (s / (float)c) : 0.f;
            g_ticket = 0;   // reset for next graph replay
        }
    }
}

// ---------------- entry point ----------------
extern "C" void kernel_launch(void* const* d_in, const int* in_sizes, int n_in,
                              void* d_out, int out_size) {
    const float* zf   = (const float*)d_in[1];
    const float* attr = (const float*)d_in[2];
    float* out = (float*)d_out;

    cudaFuncSetAttribute(k_gram_mma, cudaFuncAttributeMaxDynamicSharedMemorySize, SMEM_TOTAL);

    k_norm<<<BN / 8, 256>>>(zf, attr);
    k_gram_mma<<<NPAIRS, 256, SMEM_TOTAL>>>();
    k_rowloss_final<<<BN / 256, 256>>>(out);
}